// round 15
// baseline (speedup 1.0000x reference)
#include <cuda_runtime.h>
#include <mma.h>
using namespace nvcuda;

// ---------------- scratch ---------------------------------------------------
__device__ float g_qkv[8 * 1280 * 1024];
__device__ float g_attn[8 * 256 * 1024];
__device__ float g_col[8 * 2304 * 1024];

static __device__ __forceinline__ float to_tf32(float x) {
    return wmma::__float_to_tf32(x);
}

// cp.async helpers
static __device__ __forceinline__ void cp16(float* dst, const float* src) {
    unsigned d = (unsigned)__cvta_generic_to_shared(dst);
    asm volatile("cp.async.ca.shared.global [%0], [%1], 16;" :: "r"(d), "l"(src));
}
static __device__ __forceinline__ void cp_commit() {
    asm volatile("cp.async.commit_group;");
}
template <int Nw> static __device__ __forceinline__ void cp_wait() {
    asm volatile("cp.async.wait_group %0;" :: "n"(Nw));
}

// raw tf32 mma
static __device__ __forceinline__ void mma_tf32(
    float& d0, float& d1, float& d2, float& d3,
    unsigned a0, unsigned a1, unsigned a2, unsigned a3,
    unsigned b0, unsigned b1)
{
    asm("mma.sync.aligned.m16n8k8.row.col.f32.tf32.tf32.f32 "
        "{%0,%1,%2,%3},{%4,%5,%6,%7},{%8,%9},{%0,%1,%2,%3};"
        : "+f"(d0), "+f"(d1), "+f"(d2), "+f"(d3)
        : "r"(a0), "r"(a1), "r"(a2), "r"(a3), "r"(b0), "r"(b1));
}

#define SHFL(v, s) __shfl_sync(0xffffffffu, (v), (s))

// ---------------- sgemm: 128x256 block, 64x64 warp tile, cp.async -----------
// 8 warps as 2(m) x 4(n); warp tile 64x64 = 4x4 m16n16k8 frags.
// 32 LDS feed 16 mma per k-step (2 LDS/mma vs 3 at 64x32).
#define SG_BUF (128 * 36 + 32 * 260)     // floats per stage (A + B)
#define SG_FLOATS (2 * SG_BUF)
#define SG_SMEM_BYTES (SG_FLOATS * 4)

static __device__ void sgemm_body(
    const float* __restrict__ A, const float* __restrict__ Bp,
    float* __restrict__ Cp, int K, int N, int m0, int n0, int round_out,
    float* sg)
{
    int tid = threadIdx.x;
    int w = tid >> 5, wm = w & 1, wn = w >> 1;
    int am = tid >> 3, akq = tid & 7;       // A: rows am + p*32, k-quad akq

    wmma::fragment<wmma::accumulator, 16, 16, 8, float> c[4][4];
#pragma unroll
    for (int i = 0; i < 4; i++)
#pragma unroll
        for (int j = 0; j < 4; j++) wmma::fill_fragment(c[i][j], 0.0f);

    int nch = K >> 5;

    // prologue: stage chunk 0 into buffer 0
    {
        float* As = sg;
        float* Bs = sg + 128 * 36;
#pragma unroll
        for (int p = 0; p < 4; p++)
            cp16(&As[(am + p * 32) * 36 + akq * 4],
                 &A[(long)(m0 + am + p * 32) * K + akq * 4]);
#pragma unroll
        for (int p = 0; p < 8; p++) {
            int slot = tid + p * 256;
            int kr = slot >> 6, cq = slot & 63;
            cp16(&Bs[kr * 260 + cq * 4],
                 &Bp[(long)kr * N + n0 + cq * 4]);
        }
        cp_commit();
    }

    for (int ci = 0; ci < nch; ci++) {
        cp_wait<0>();
        __syncthreads();

        if (ci + 1 < nch) {
            int k0n = (ci + 1) << 5;
            float* As = sg + ((ci + 1) & 1) * SG_BUF;
            float* Bs = As + 128 * 36;
#pragma unroll
            for (int p = 0; p < 4; p++)
                cp16(&As[(am + p * 32) * 36 + akq * 4],
                     &A[(long)(m0 + am + p * 32) * K + k0n + akq * 4]);
#pragma unroll
            for (int p = 0; p < 8; p++) {
                int slot = tid + p * 256;
                int kr = slot >> 6, cq = slot & 63;
                cp16(&Bs[kr * 260 + cq * 4],
                     &Bp[(long)(k0n + kr) * N + n0 + cq * 4]);
            }
            cp_commit();
        }

        float* As = sg + (ci & 1) * SG_BUF;
        float* Bs = As + 128 * 36;
#pragma unroll
        for (int kk = 0; kk < 32; kk += 8) {
            wmma::fragment<wmma::matrix_a, 16, 16, 8, wmma::precision::tf32,
                           wmma::row_major> a[4];
            wmma::fragment<wmma::matrix_b, 16, 16, 8, wmma::precision::tf32,
                           wmma::row_major> bf[4];
#pragma unroll
            for (int i = 0; i < 4; i++)
                wmma::load_matrix_sync(a[i],
                    &As[(wm * 64 + i * 16) * 36 + kk], 36);
#pragma unroll
            for (int j = 0; j < 4; j++)
                wmma::load_matrix_sync(bf[j],
                    &Bs[kk * 260 + wn * 64 + j * 16], 260);
#pragma unroll
            for (int i = 0; i < 4; i++)
#pragma unroll
                for (int j = 0; j < 4; j++)
                    wmma::mma_sync(c[i][j], a[i], bf[j], c[i][j]);
        }
    }

    if (round_out) {
#pragma unroll
        for (int i = 0; i < 4; i++)
#pragma unroll
            for (int j = 0; j < 4; j++)
#pragma unroll
                for (int t = 0; t < c[i][j].num_elements; t++)
                    c[i][j].x[t] = to_tf32(c[i][j].x[t]);
    }
#pragma unroll
    for (int i = 0; i < 4; i++)
#pragma unroll
        for (int j = 0; j < 4; j++)
            wmma::store_matrix_sync(
                &Cp[(long)(m0 + wm * 64 + i * 16) * N + n0 + wn * 64 + j * 16],
                c[i][j], N, wmma::mem_row_major);
}

// ---------------- attn body (R12 known-good) --------------------------------
#define AT_KS 0
#define AT_VS (2 * 64 * 72)
#define AT_PS (AT_VS + 2 * 32 * 68)
#define AT_EH (AT_PS + 64 * 68)
#define AT_EW (AT_EH + 64 * 36)
#define AT_LP (AT_EW + 64 * 36)
#define AT_LI (AT_LP + 128)
#define AT_FLOATS (AT_LI + 64)
#define ATTN_SMEM_BYTES (AT_FLOATS * 4)

static __device__ void attn_body(
    const float* __restrict__ krh, const float* __restrict__ krw,
    int s0, int n, int b, float* smx)
{
    float* K0 = smx + AT_KS;
    float* V0 = smx + AT_VS;
    float* Ps = smx + AT_PS;
    float* EH = smx + AT_EH;
    float* EW = smx + AT_EW;
    float* lp = smx + AT_LP;
    float* li = smx + AT_LI;

    int tid = threadIdx.x, w = tid >> 5, lane = tid & 31;
    int qr = lane >> 2, qc = lane & 3;

    const float* qb = g_qkv + ((long)(b * 1280 + n * 64)) * 1024;
    const float* kb = qb + 512 * 1024;
    const float* vb = g_qkv + ((long)(b * 1280 + 1024 + n * 32)) * 1024;

    int sw  = (w & 3) * 16;
    int twq = (w >> 2) * 32;
    int th  = w >> 2;

#pragma unroll
    for (int p = 0; p < 4; p++) {
        int slot = tid + p * 256;
        int c = slot >> 4, sq = slot & 15;
        float4 v = *(const float4*)&qb[(long)c * 1024 + s0 + sq * 4];
        float* d = &K0[c * 72 + sq * 4];
        d[0] = v.x * 0.125f; d[1] = v.y * 0.125f;
        d[2] = v.z * 0.125f; d[3] = v.w * 0.125f;
    }
    for (int i = tid; i < 4096; i += 256) {
        int ss = i >> 6, c = i & 63;
        int ws = ss & 31, hs = (s0 + ss) >> 5;
        int sT = ws * 32 + hs;
        Ps[ss * 68 + c] = qb[(long)c * 1024 + sT] * 0.125f;
    }
    __syncthreads();

    unsigned qf[8][4];
#pragma unroll
    for (int k = 0; k < 8; k++) {
        int c0 = k * 8;
        qf[k][0] = __float_as_uint(K0[(c0 + qc) * 72 + sw + qr]);
        qf[k][1] = __float_as_uint(K0[(c0 + qc) * 72 + sw + qr + 8]);
        qf[k][2] = __float_as_uint(K0[(c0 + qc + 4) * 72 + sw + qr]);
        qf[k][3] = __float_as_uint(K0[(c0 + qc + 4) * 72 + sw + qr + 8]);
    }
    __syncthreads();

#pragma unroll
    for (int pass = 0; pass < 2; pass++) {
        const float* tab = pass ? krw : krh;
        for (int i = tid; i < 4608; i += 256) {
            int c = i / 72, d = i % 72;
            K0[i] = (d < 63) ? to_tf32(tab[c * 63 + d]) : 0.f;
        }
        __syncthreads();
        wmma::fragment<wmma::accumulator, 16, 16, 8, float> tf[2];
        wmma::fill_fragment(tf[0], 0.f);
        wmma::fill_fragment(tf[1], 0.f);
#pragma unroll
        for (int kk = 0; kk < 64; kk += 8) {
            wmma::fragment<wmma::matrix_a, 16, 16, 8, wmma::precision::tf32,
                           wmma::row_major> a;
            wmma::load_matrix_sync(a, &Ps[sw * 68 + kk], 68);
#pragma unroll
            for (int j = 0; j < 2; j++) {
                wmma::fragment<wmma::matrix_b, 16, 16, 8, wmma::precision::tf32,
                               wmma::row_major> bf;
                wmma::load_matrix_sync(bf, &K0[kk * 72 + twq + j * 16], 72);
                wmma::mma_sync(tf[j], a, bf, tf[j]);
            }
        }
        __syncthreads();
#pragma unroll
        for (int j = 0; j < 2; j++)
            wmma::store_matrix_sync(&K0[sw * 72 + twq + j * 16], tf[j], 72,
                                    wmma::mem_row_major);
        __syncthreads();
        float* dst = pass ? EW : EH;
        for (int i = tid; i < 2048; i += 256) {
            int es = i >> 5, d = i & 31;
            int base = pass ? ((s0 + es) >> 5) : (es & 31);
            dst[es * 36 + d] = __expf(K0[es * 72 + d - base + 31]);
        }
        __syncthreads();
    }

    int kc = tid >> 4, ktq = tid & 15;
    int vc = tid >> 4, vtq = tid & 15;

#pragma unroll
    for (int p = 0; p < 4; p++)
        cp16(&K0[(kc + p * 16) * 72 + ktq * 4],
             &kb[(long)(kc + p * 16) * 1024 + ktq * 4]);
#pragma unroll
    for (int p = 0; p < 2; p++)
        cp16(&V0[(vc + p * 16) * 68 + vtq * 4],
             &vb[(long)(vc + p * 16) * 1024 + vtq * 4]);
    cp_commit();

    float l_lo = 0.f, l_hi = 0.f;
    float O[4][4] = {};
    int srcA = (lane & ~3) + (qc >> 1);
    int srcB = srcA + 2;
    bool odd = (qc & 1) != 0;

    for (int ti = 0; ti < 16; ti++) {
        int t0 = ti * 64;
        float* Kb = K0 + (ti & 1) * 4608;
        float* Vb = V0 + (ti & 1) * 2176;

        cp_wait<0>();
        __syncthreads();

        if (ti < 15) {
            float* Kn = K0 + ((ti + 1) & 1) * 4608;
            float* Vn = V0 + ((ti + 1) & 1) * 2176;
            int t0n = t0 + 64;
#pragma unroll
            for (int p = 0; p < 4; p++)
                cp16(&Kn[(kc + p * 16) * 72 + ktq * 4],
                     &kb[(long)(kc + p * 16) * 1024 + t0n + ktq * 4]);
#pragma unroll
            for (int p = 0; p < 2; p++)
                cp16(&Vn[(vc + p * 16) * 68 + vtq * 4],
                     &vb[(long)(vc + p * 16) * 1024 + t0n + vtq * 4]);
            cp_commit();
        }

        float p4[4][4] = {};
#pragma unroll
        for (int k = 0; k < 8; k++) {
            int c0 = k * 8;
#pragma unroll
            for (int j = 0; j < 4; j++) {
                unsigned b0 = __float_as_uint(Kb[(c0 + qc) * 72 + twq + j * 8 + qr]);
                unsigned b1 = __float_as_uint(Kb[(c0 + qc + 4) * 72 + twq + j * 8 + qr]);
                mma_tf32(p4[j][0], p4[j][1], p4[j][2], p4[j][3],
                         qf[k][0], qf[k][1], qf[k][2], qf[k][3], b0, b1);
            }
        }

        {
            int ht = (t0 + twq) >> 5;
            float ew0 = EW[(sw + qr) * 36 + ht];
            float ew1 = EW[(sw + qr + 8) * 36 + ht];
#pragma unroll
            for (int j = 0; j < 4; j++) {
                int tl0 = twq + j * 8;
                int wt = (tl0 + 2 * qc) & 31;
                float2 eh0 = *(const float2*)&EH[(sw + qr) * 36 + wt];
                float2 eh1 = *(const float2*)&EH[(sw + qr + 8) * 36 + wt];
                float e0 = __expf(p4[j][0]) * eh0.x * ew0;
                float e1 = __expf(p4[j][1]) * eh0.y * ew0;
                float e2 = __expf(p4[j][2]) * eh1.x * ew1;
                float e3 = __expf(p4[j][3]) * eh1.y * ew1;
                l_lo += e0 + e1;
                l_hi += e2 + e3;
                p4[j][0] = to_tf32(e0); p4[j][1] = to_tf32(e1);
                p4[j][2] = to_tf32(e2); p4[j][3] = to_tf32(e3);
            }
        }

#pragma unroll
        for (int ko = 0; ko < 4; ko++) {
            float sA0 = SHFL(p4[ko][0], srcA), sA1 = SHFL(p4[ko][1], srcA);
            float sA2 = SHFL(p4[ko][2], srcA), sA3 = SHFL(p4[ko][3], srcA);
            float sB0 = SHFL(p4[ko][0], srcB), sB1 = SHFL(p4[ko][1], srcB);
            float sB2 = SHFL(p4[ko][2], srcB), sB3 = SHFL(p4[ko][3], srcB);
            unsigned a0 = __float_as_uint(odd ? sA1 : sA0);
            unsigned a1 = __float_as_uint(odd ? sA3 : sA2);
            unsigned a2 = __float_as_uint(odd ? sB1 : sB0);
            unsigned a3 = __float_as_uint(odd ? sB3 : sB2);
            int kt = twq + ko * 8;
#pragma unroll
            for (int nf = 0; nf < 4; nf++) {
                unsigned b0 = __float_as_uint(Vb[(nf * 8 + qr) * 68 + kt + qc]);
                unsigned b1 = __float_as_uint(Vb[(nf * 8 + qr) * 68 + kt + qc + 4]);
                mma_tf32(O[nf][0], O[nf][1], O[nf][2], O[nf][3],
                         a0, a1, a2, a3, b0, b1);
            }
        }
    }

    l_lo += __shfl_xor_sync(0xffffffffu, l_lo, 1);
    l_lo += __shfl_xor_sync(0xffffffffu, l_lo, 2);
    l_hi += __shfl_xor_sync(0xffffffffu, l_hi, 1);
    l_hi += __shfl_xor_sync(0xffffffffu, l_hi, 2);
    if (qc == 0) {
        lp[(sw + qr) * 2 + th] = l_lo;
        lp[(sw + qr + 8) * 2 + th] = l_hi;
    }
    if (th == 1) {
#pragma unroll
        for (int nf = 0; nf < 4; nf++) {
            *(float2*)&Ps[(sw + qr) * 68 + nf * 8 + 2 * qc] =
                make_float2(O[nf][0], O[nf][1]);
            *(float2*)&Ps[(sw + qr + 8) * 68 + nf * 8 + 2 * qc] =
                make_float2(O[nf][2], O[nf][3]);
        }
    }
    __syncthreads();
    if (tid < 64) li[tid] = 1.0f / (lp[tid * 2] + lp[tid * 2 + 1]);
    if (th == 0) {
#pragma unroll
        for (int nf = 0; nf < 4; nf++) {
            float2 q0 = *(const float2*)&Ps[(sw + qr) * 68 + nf * 8 + 2 * qc];
            float2 q1 = *(const float2*)&Ps[(sw + qr + 8) * 68 + nf * 8 + 2 * qc];
            *(float2*)&Ps[(sw + qr) * 68 + nf * 8 + 2 * qc] =
                make_float2(O[nf][0] + q0.x, O[nf][1] + q0.y);
            *(float2*)&Ps[(sw + qr + 8) * 68 + nf * 8 + 2 * qc] =
                make_float2(O[nf][2] + q1.x, O[nf][3] + q1.y);
        }
    }
    __syncthreads();

    float* ob = g_attn + ((long)(b * 256 + n * 32)) * 1024 + s0;
    for (int i = tid; i < 2048; i += 256) {
        int cv = i >> 6, s = i & 63;
        ob[(long)cv * 1024 + s] = to_tf32(Ps[s * 68 + cv] * li[s]);
    }
}

// ---------------- launch A: qkv GEMM (320 CTAs) + im2col (1152 CTAs) --------
__global__ __launch_bounds__(256, 2) void kernelA(
    const float* __restrict__ w_qkv, const float* __restrict__ x,
    float* __restrict__ gq)
{
    extern __shared__ float sm[];
    int bid = blockIdx.x;
    if (bid < 320) {
        int n0 = (bid & 3) * 256;
        int m0 = ((bid >> 2) % 10) * 128;
        int b = bid / 40;
        sgemm_body(w_qkv, x + (long)b * 256 * 1024,
                   gq + (long)b * 1280 * 1024, 256, 1024, m0, n0, 1, sm);
        return;
    }
    int id = bid - 320;
    int tid = threadIdx.x;
    int s = tid * 4;
    int h = s >> 5, w0 = s & 31;
#pragma unroll
    for (int p = 0; p < 16; p++) {
        int inst = id * 16 + p;
        int b = inst / 2304, row = inst % 2304;
        int c = row / 9, tap = row % 9;
        int dh = tap / 3 - 1, dw = tap % 3 - 1;
        int hh = h + dh;
        float4 v = make_float4(0.f, 0.f, 0.f, 0.f);
        if (hh >= 0 && hh < 32) {
            const float* xp = x + ((long)(b * 256 + c) * 32 + hh) * 32;
            int w;
            w = w0 + 0 + dw; if (w >= 0 && w < 32) v.x = to_tf32(xp[w]);
            w = w0 + 1 + dw; if (w >= 0 && w < 32) v.y = to_tf32(xp[w]);
            w = w0 + 2 + dw; if (w >= 0 && w < 32) v.z = to_tf32(xp[w]);
            w = w0 + 3 + dw; if (w >= 0 && w < 32) v.w = to_tf32(xp[w]);
        }
        *(float4*)&g_col[((long)b * 2304 + row) * 1024 + s] = v;
    }
}

// ---------------- launch B: conv GEMM (64 CTAs, first) + attn (1024) --------
__global__ __launch_bounds__(256, 2) void kernelB(
    const float* __restrict__ krh, const float* __restrict__ krw,
    const float* __restrict__ w_conv, float* __restrict__ out)
{
    extern __shared__ float sm[];
    int bid = blockIdx.x;
    if (bid < 64) {
        int n0 = (bid & 3) * 256;
        int m0 = ((bid >> 2) & 1) * 128;
        int b = bid >> 3;
        sgemm_body(w_conv, g_col + (long)b * 2304 * 1024,
                   out + (long)b * 512 * 1024, 2304, 1024, m0, n0, 0, sm);
        return;
    }
    int a = bid - 64;
    int s0 = (a & 15) * 64;
    int n = (a >> 4) & 7;
    int b = a >> 7;
    attn_body(krh, krw, s0, n, b, sm);
}

// ---------------- launch C: w_out GEMM (64 CTAs) ----------------------------
__global__ __launch_bounds__(256, 2) void kernelC(
    const float* __restrict__ w_out, float* __restrict__ out)
{
    extern __shared__ float sm[];
    int bid = blockIdx.x;
    int n0 = (bid & 3) * 256;
    int m0 = ((bid >> 2) & 1) * 128;
    int b = bid >> 3;
    sgemm_body(w_out, g_attn + (long)b * 256 * 1024,
               out + (long)b * 512 * 1024 + 256 * 1024,
               256, 1024, m0, n0, 0, sm);
}

// ---------------- launch ----------------------------------------------------
extern "C" void kernel_launch(void* const* d_in, const int* in_sizes, int n_in,
                              void* d_out, int out_size)
{
    const float* x      = (const float*)d_in[0];
    const float* w_qkv  = (const float*)d_in[1];
    const float* w_conv = (const float*)d_in[2];
    const float* w_out  = (const float*)d_in[3];
    const float* krh    = (const float*)d_in[4];
    const float* krw    = (const float*)d_in[5];
    float* out = (float*)d_out;

    float* gq; cudaGetSymbolAddress((void**)&gq, g_qkv);

    int sgB = SG_SMEM_BYTES, atB = ATTN_SMEM_BYTES;
    int bMax = sgB > atB ? sgB : atB;
    cudaFuncSetAttribute(kernelA, cudaFuncAttributeMaxDynamicSharedMemorySize,
                         sgB);
    cudaFuncSetAttribute(kernelB, cudaFuncAttributeMaxDynamicSharedMemorySize,
                         bMax);
    cudaFuncSetAttribute(kernelC, cudaFuncAttributeMaxDynamicSharedMemorySize,
                         sgB);

    // A) qkv projection + im2col (independent, grid-merged)
    kernelA<<<320 + 1152, 256, sgB>>>(w_qkv, x, gq);

    // B) conv GEMM (long CTAs first) + fused attention (grid-merged)
    kernelB<<<64 + 1024, 256, bMax>>>(krh, krw, w_conv, out);

    // C) output projection
    kernelC<<<64, 256, sgB>>>(w_out, out);
}

// round 16
// speedup vs baseline: 3.3400x; 3.3400x over previous
#include <cuda_runtime.h>
#include <mma.h>
using namespace nvcuda;

// ---------------- scratch ---------------------------------------------------
__device__ float g_qkv[8 * 1280 * 1024];
__device__ float g_attn[8 * 256 * 1024];
__device__ float g_col[8 * 2304 * 1024];
__device__ unsigned g_cnt[8];            // per-batch attn completion counters

static __device__ __forceinline__ float to_tf32(float x) {
    return wmma::__float_to_tf32(x);
}

// cp.async helpers
static __device__ __forceinline__ void cp16(float* dst, const float* src) {
    unsigned d = (unsigned)__cvta_generic_to_shared(dst);
    asm volatile("cp.async.ca.shared.global [%0], [%1], 16;" :: "r"(d), "l"(src));
}
static __device__ __forceinline__ void cp_commit() {
    asm volatile("cp.async.commit_group;");
}
template <int Nw> static __device__ __forceinline__ void cp_wait() {
    asm volatile("cp.async.wait_group %0;" :: "n"(Nw));
}

// raw tf32 mma
static __device__ __forceinline__ void mma_tf32(
    float& d0, float& d1, float& d2, float& d3,
    unsigned a0, unsigned a1, unsigned a2, unsigned a3,
    unsigned b0, unsigned b1)
{
    asm("mma.sync.aligned.m16n8k8.row.col.f32.tf32.tf32.f32 "
        "{%0,%1,%2,%3},{%4,%5,%6,%7},{%8,%9},{%0,%1,%2,%3};"
        : "+f"(d0), "+f"(d1), "+f"(d2), "+f"(d3)
        : "r"(a0), "r"(a1), "r"(a2), "r"(a3), "r"(b0), "r"(b1));
}

#define SHFL(v, s) __shfl_sync(0xffffffffu, (v), (s))

// ---------------- sgemm: 128x128 block, 64x32 warp tile (R12 known-good) ----
#define SG_BUF (128 * 36 + 32 * 132)     // floats per stage (A + B)
#define SG_FLOATS (2 * SG_BUF)
#define SG_SMEM_BYTES (SG_FLOATS * 4)

static __device__ void sgemm_body(
    const float* __restrict__ A, const float* __restrict__ Bp,
    float* __restrict__ Cp, int K, int N, int m0, int n0, int round_out,
    float* sg)
{
    int tid = threadIdx.x;
    int w = tid >> 5, wm = w & 1, wn = w >> 1;
    int am = tid >> 3, akq = tid & 7;
    int bk = tid >> 5, bnq = tid & 31;

    wmma::fragment<wmma::accumulator, 16, 16, 8, float> c[4][2];
#pragma unroll
    for (int i = 0; i < 4; i++)
#pragma unroll
        for (int j = 0; j < 2; j++) wmma::fill_fragment(c[i][j], 0.0f);

    int nch = K >> 5;

    {
        float* As = sg;
        float* Bs = sg + 128 * 36;
#pragma unroll
        for (int p = 0; p < 4; p++)
            cp16(&As[(am + p * 32) * 36 + akq * 4],
                 &A[(long)(m0 + am + p * 32) * K + akq * 4]);
#pragma unroll
        for (int p = 0; p < 4; p++)
            cp16(&Bs[(bk + p * 8) * 132 + bnq * 4],
                 &Bp[(long)(bk + p * 8) * N + n0 + bnq * 4]);
        cp_commit();
    }

    for (int ci = 0; ci < nch; ci++) {
        cp_wait<0>();
        __syncthreads();

        if (ci + 1 < nch) {
            int k0n = (ci + 1) << 5;
            float* As = sg + ((ci + 1) & 1) * SG_BUF;
            float* Bs = As + 128 * 36;
#pragma unroll
            for (int p = 0; p < 4; p++)
                cp16(&As[(am + p * 32) * 36 + akq * 4],
                     &A[(long)(m0 + am + p * 32) * K + k0n + akq * 4]);
#pragma unroll
            for (int p = 0; p < 4; p++)
                cp16(&Bs[(bk + p * 8) * 132 + bnq * 4],
                     &Bp[(long)(k0n + bk + p * 8) * N + n0 + bnq * 4]);
            cp_commit();
        }

        float* As = sg + (ci & 1) * SG_BUF;
        float* Bs = As + 128 * 36;
#pragma unroll
        for (int kk = 0; kk < 32; kk += 8) {
            wmma::fragment<wmma::matrix_a, 16, 16, 8, wmma::precision::tf32,
                           wmma::row_major> a[4];
            wmma::fragment<wmma::matrix_b, 16, 16, 8, wmma::precision::tf32,
                           wmma::row_major> bf[2];
#pragma unroll
            for (int i = 0; i < 4; i++)
                wmma::load_matrix_sync(a[i],
                    &As[(wm * 64 + i * 16) * 36 + kk], 36);
#pragma unroll
            for (int j = 0; j < 2; j++)
                wmma::load_matrix_sync(bf[j],
                    &Bs[kk * 132 + wn * 32 + j * 16], 132);
#pragma unroll
            for (int i = 0; i < 4; i++)
#pragma unroll
                for (int j = 0; j < 2; j++)
                    wmma::mma_sync(c[i][j], a[i], bf[j], c[i][j]);
        }
    }

    if (round_out) {
#pragma unroll
        for (int i = 0; i < 4; i++)
#pragma unroll
            for (int j = 0; j < 2; j++)
#pragma unroll
                for (int t = 0; t < c[i][j].num_elements; t++)
                    c[i][j].x[t] = to_tf32(c[i][j].x[t]);
    }
#pragma unroll
    for (int i = 0; i < 4; i++)
#pragma unroll
        for (int j = 0; j < 2; j++)
            wmma::store_matrix_sync(
                &Cp[(long)(m0 + wm * 64 + i * 16) * N + n0 + wn * 32 + j * 16],
                c[i][j], N, wmma::mem_row_major);
}

// ---------------- attn body (R12 known-good + completion signal) ------------
#define AT_KS 0
#define AT_VS (2 * 64 * 72)
#define AT_PS (AT_VS + 2 * 32 * 68)
#define AT_EH (AT_PS + 64 * 68)
#define AT_EW (AT_EH + 64 * 36)
#define AT_LP (AT_EW + 64 * 36)
#define AT_LI (AT_LP + 128)
#define AT_FLOATS (AT_LI + 64)
#define ATTN_SMEM_BYTES (AT_FLOATS * 4)

static __device__ void attn_body(
    const float* __restrict__ krh, const float* __restrict__ krw,
    int s0, int n, int b, float* smx)
{
    float* K0 = smx + AT_KS;
    float* V0 = smx + AT_VS;
    float* Ps = smx + AT_PS;
    float* EH = smx + AT_EH;
    float* EW = smx + AT_EW;
    float* lp = smx + AT_LP;
    float* li = smx + AT_LI;

    int tid = threadIdx.x, w = tid >> 5, lane = tid & 31;
    int qr = lane >> 2, qc = lane & 3;

    const float* qb = g_qkv + ((long)(b * 1280 + n * 64)) * 1024;
    const float* kb = qb + 512 * 1024;
    const float* vb = g_qkv + ((long)(b * 1280 + 1024 + n * 32)) * 1024;

    int sw  = (w & 3) * 16;
    int twq = (w >> 2) * 32;
    int th  = w >> 2;

#pragma unroll
    for (int p = 0; p < 4; p++) {
        int slot = tid + p * 256;
        int c = slot >> 4, sq = slot & 15;
        float4 v = *(const float4*)&qb[(long)c * 1024 + s0 + sq * 4];
        float* d = &K0[c * 72 + sq * 4];
        d[0] = v.x * 0.125f; d[1] = v.y * 0.125f;
        d[2] = v.z * 0.125f; d[3] = v.w * 0.125f;
    }
    for (int i = tid; i < 4096; i += 256) {
        int ss = i >> 6, c = i & 63;
        int ws = ss & 31, hs = (s0 + ss) >> 5;
        int sT = ws * 32 + hs;
        Ps[ss * 68 + c] = qb[(long)c * 1024 + sT] * 0.125f;
    }
    __syncthreads();

    unsigned qf[8][4];
#pragma unroll
    for (int k = 0; k < 8; k++) {
        int c0 = k * 8;
        qf[k][0] = __float_as_uint(K0[(c0 + qc) * 72 + sw + qr]);
        qf[k][1] = __float_as_uint(K0[(c0 + qc) * 72 + sw + qr + 8]);
        qf[k][2] = __float_as_uint(K0[(c0 + qc + 4) * 72 + sw + qr]);
        qf[k][3] = __float_as_uint(K0[(c0 + qc + 4) * 72 + sw + qr + 8]);
    }
    __syncthreads();

#pragma unroll
    for (int pass = 0; pass < 2; pass++) {
        const float* tab = pass ? krw : krh;
        for (int i = tid; i < 4608; i += 256) {
            int c = i / 72, d = i % 72;
            K0[i] = (d < 63) ? to_tf32(tab[c * 63 + d]) : 0.f;
        }
        __syncthreads();
        wmma::fragment<wmma::accumulator, 16, 16, 8, float> tf[2];
        wmma::fill_fragment(tf[0], 0.f);
        wmma::fill_fragment(tf[1], 0.f);
#pragma unroll
        for (int kk = 0; kk < 64; kk += 8) {
            wmma::fragment<wmma::matrix_a, 16, 16, 8, wmma::precision::tf32,
                           wmma::row_major> a;
            wmma::load_matrix_sync(a, &Ps[sw * 68 + kk], 68);
#pragma unroll
            for (int j = 0; j < 2; j++) {
                wmma::fragment<wmma::matrix_b, 16, 16, 8, wmma::precision::tf32,
                               wmma::row_major> bf;
                wmma::load_matrix_sync(bf, &K0[kk * 72 + twq + j * 16], 72);
                wmma::mma_sync(tf[j], a, bf, tf[j]);
            }
        }
        __syncthreads();
#pragma unroll
        for (int j = 0; j < 2; j++)
            wmma::store_matrix_sync(&K0[sw * 72 + twq + j * 16], tf[j], 72,
                                    wmma::mem_row_major);
        __syncthreads();
        float* dst = pass ? EW : EH;
        for (int i = tid; i < 2048; i += 256) {
            int es = i >> 5, d = i & 31;
            int base = pass ? ((s0 + es) >> 5) : (es & 31);
            dst[es * 36 + d] = __expf(K0[es * 72 + d - base + 31]);
        }
        __syncthreads();
    }

    int kc = tid >> 4, ktq = tid & 15;
    int vc = tid >> 4, vtq = tid & 15;

#pragma unroll
    for (int p = 0; p < 4; p++)
        cp16(&K0[(kc + p * 16) * 72 + ktq * 4],
             &kb[(long)(kc + p * 16) * 1024 + ktq * 4]);
#pragma unroll
    for (int p = 0; p < 2; p++)
        cp16(&V0[(vc + p * 16) * 68 + vtq * 4],
             &vb[(long)(vc + p * 16) * 1024 + vtq * 4]);
    cp_commit();

    float l_lo = 0.f, l_hi = 0.f;
    float O[4][4] = {};
    int srcA = (lane & ~3) + (qc >> 1);
    int srcB = srcA + 2;
    bool odd = (qc & 1) != 0;

    for (int ti = 0; ti < 16; ti++) {
        int t0 = ti * 64;
        float* Kb = K0 + (ti & 1) * 4608;
        float* Vb = V0 + (ti & 1) * 2176;

        cp_wait<0>();
        __syncthreads();

        if (ti < 15) {
            float* Kn = K0 + ((ti + 1) & 1) * 4608;
            float* Vn = V0 + ((ti + 1) & 1) * 2176;
            int t0n = t0 + 64;
#pragma unroll
            for (int p = 0; p < 4; p++)
                cp16(&Kn[(kc + p * 16) * 72 + ktq * 4],
                     &kb[(long)(kc + p * 16) * 1024 + t0n + ktq * 4]);
#pragma unroll
            for (int p = 0; p < 2; p++)
                cp16(&Vn[(vc + p * 16) * 68 + vtq * 4],
                     &vb[(long)(vc + p * 16) * 1024 + t0n + vtq * 4]);
            cp_commit();
        }

        float p4[4][4] = {};
#pragma unroll
        for (int k = 0; k < 8; k++) {
            int c0 = k * 8;
#pragma unroll
            for (int j = 0; j < 4; j++) {
                unsigned b0 = __float_as_uint(Kb[(c0 + qc) * 72 + twq + j * 8 + qr]);
                unsigned b1 = __float_as_uint(Kb[(c0 + qc + 4) * 72 + twq + j * 8 + qr]);
                mma_tf32(p4[j][0], p4[j][1], p4[j][2], p4[j][3],
                         qf[k][0], qf[k][1], qf[k][2], qf[k][3], b0, b1);
            }
        }

        {
            int ht = (t0 + twq) >> 5;
            float ew0 = EW[(sw + qr) * 36 + ht];
            float ew1 = EW[(sw + qr + 8) * 36 + ht];
#pragma unroll
            for (int j = 0; j < 4; j++) {
                int tl0 = twq + j * 8;
                int wt = (tl0 + 2 * qc) & 31;
                float2 eh0 = *(const float2*)&EH[(sw + qr) * 36 + wt];
                float2 eh1 = *(const float2*)&EH[(sw + qr + 8) * 36 + wt];
                float e0 = __expf(p4[j][0]) * eh0.x * ew0;
                float e1 = __expf(p4[j][1]) * eh0.y * ew0;
                float e2 = __expf(p4[j][2]) * eh1.x * ew1;
                float e3 = __expf(p4[j][3]) * eh1.y * ew1;
                l_lo += e0 + e1;
                l_hi += e2 + e3;
                p4[j][0] = to_tf32(e0); p4[j][1] = to_tf32(e1);
                p4[j][2] = to_tf32(e2); p4[j][3] = to_tf32(e3);
            }
        }

#pragma unroll
        for (int ko = 0; ko < 4; ko++) {
            float sA0 = SHFL(p4[ko][0], srcA), sA1 = SHFL(p4[ko][1], srcA);
            float sA2 = SHFL(p4[ko][2], srcA), sA3 = SHFL(p4[ko][3], srcA);
            float sB0 = SHFL(p4[ko][0], srcB), sB1 = SHFL(p4[ko][1], srcB);
            float sB2 = SHFL(p4[ko][2], srcB), sB3 = SHFL(p4[ko][3], srcB);
            unsigned a0 = __float_as_uint(odd ? sA1 : sA0);
            unsigned a1 = __float_as_uint(odd ? sA3 : sA2);
            unsigned a2 = __float_as_uint(odd ? sB1 : sB0);
            unsigned a3 = __float_as_uint(odd ? sB3 : sB2);
            int kt = twq + ko * 8;
#pragma unroll
            for (int nf = 0; nf < 4; nf++) {
                unsigned b0 = __float_as_uint(Vb[(nf * 8 + qr) * 68 + kt + qc]);
                unsigned b1 = __float_as_uint(Vb[(nf * 8 + qr) * 68 + kt + qc + 4]);
                mma_tf32(O[nf][0], O[nf][1], O[nf][2], O[nf][3],
                         a0, a1, a2, a3, b0, b1);
            }
        }
    }

    l_lo += __shfl_xor_sync(0xffffffffu, l_lo, 1);
    l_lo += __shfl_xor_sync(0xffffffffu, l_lo, 2);
    l_hi += __shfl_xor_sync(0xffffffffu, l_hi, 1);
    l_hi += __shfl_xor_sync(0xffffffffu, l_hi, 2);
    if (qc == 0) {
        lp[(sw + qr) * 2 + th] = l_lo;
        lp[(sw + qr + 8) * 2 + th] = l_hi;
    }
    if (th == 1) {
#pragma unroll
        for (int nf = 0; nf < 4; nf++) {
            *(float2*)&Ps[(sw + qr) * 68 + nf * 8 + 2 * qc] =
                make_float2(O[nf][0], O[nf][1]);
            *(float2*)&Ps[(sw + qr + 8) * 68 + nf * 8 + 2 * qc] =
                make_float2(O[nf][2], O[nf][3]);
        }
    }
    __syncthreads();
    if (tid < 64) li[tid] = 1.0f / (lp[tid * 2] + lp[tid * 2 + 1]);
    if (th == 0) {
#pragma unroll
        for (int nf = 0; nf < 4; nf++) {
            float2 q0 = *(const float2*)&Ps[(sw + qr) * 68 + nf * 8 + 2 * qc];
            float2 q1 = *(const float2*)&Ps[(sw + qr + 8) * 68 + nf * 8 + 2 * qc];
            *(float2*)&Ps[(sw + qr) * 68 + nf * 8 + 2 * qc] =
                make_float2(O[nf][0] + q0.x, O[nf][1] + q0.y);
            *(float2*)&Ps[(sw + qr + 8) * 68 + nf * 8 + 2 * qc] =
                make_float2(O[nf][2] + q1.x, O[nf][3] + q1.y);
        }
    }
    __syncthreads();

    float* ob = g_attn + ((long)(b * 256 + n * 32)) * 1024 + s0;
    for (int i = tid; i < 2048; i += 256) {
        int cv = i >> 6, s = i & 63;
        ob[(long)cv * 1024 + s] = to_tf32(Ps[s * 68 + cv] * li[s]);
    }

    // signal completion for this batch (release: fence before atomic)
    __threadfence();
    __syncthreads();
    if (tid == 0) atomicAdd(&g_cnt[b], 1u);
}

// ---------------- launch A: qkv GEMM (640) + im2col (1152) + cnt reset ------
__global__ __launch_bounds__(256, 2) void kernelA(
    const float* __restrict__ w_qkv, const float* __restrict__ x,
    float* __restrict__ gq)
{
    extern __shared__ float sm[];
    int bid = blockIdx.x;
    if (bid < 640) {
        int n0 = (bid & 7) * 128;
        int m0 = ((bid >> 3) % 10) * 128;
        int b = bid / 80;
        sgemm_body(w_qkv, x + (long)b * 256 * 1024,
                   gq + (long)b * 1280 * 1024, 256, 1024, m0, n0, 1, sm);
        return;
    }
    int id = bid - 640;
    int tid = threadIdx.x;
    if (id == 0 && tid < 8) g_cnt[tid] = 0;   // reset counters every launch
    int s = tid * 4;
    int h = s >> 5, w0 = s & 31;
#pragma unroll
    for (int p = 0; p < 16; p++) {
        int inst = id * 16 + p;
        int b = inst / 2304, row = inst % 2304;
        int c = row / 9, tap = row % 9;
        int dh = tap / 3 - 1, dw = tap % 3 - 1;
        int hh = h + dh;
        float4 v = make_float4(0.f, 0.f, 0.f, 0.f);
        if (hh >= 0 && hh < 32) {
            const float* xp = x + ((long)(b * 256 + c) * 32 + hh) * 32;
            int w;
            w = w0 + 0 + dw; if (w >= 0 && w < 32) v.x = to_tf32(xp[w]);
            w = w0 + 1 + dw; if (w >= 0 && w < 32) v.y = to_tf32(xp[w]);
            w = w0 + 2 + dw; if (w >= 0 && w < 32) v.z = to_tf32(xp[w]);
            w = w0 + 3 + dw; if (w >= 0 && w < 32) v.w = to_tf32(xp[w]);
        }
        *(float4*)&g_col[((long)b * 2304 + row) * 1024 + s] = v;
    }
}

// ---------------- launch B: conv (128) + attn (1024) + w_out (128, gated) ---
__global__ __launch_bounds__(256, 2) void kernelB(
    const float* __restrict__ krh, const float* __restrict__ krw,
    const float* __restrict__ w_conv, const float* __restrict__ w_out,
    float* __restrict__ out)
{
    extern __shared__ float sm[];
    int bid = blockIdx.x;
    int tid = threadIdx.x;
    if (bid < 128) {
        int n0 = (bid & 7) * 128;
        int m0 = ((bid >> 3) & 1) * 128;
        int b = bid >> 4;
        sgemm_body(w_conv, g_col + (long)b * 2304 * 1024,
                   out + (long)b * 512 * 1024, 2304, 1024, m0, n0, 0, sm);
        return;
    }
    if (bid < 1152) {
        int a = bid - 128;
        int s0 = (a & 15) * 64;
        int n = (a >> 4) & 7;
        int b = a >> 7;
        attn_body(krh, krw, s0, n, b, sm);
        return;
    }
    // w_out: gated on the 128 attn CTAs of its batch
    int bid2 = bid - 1152;
    int n0 = (bid2 & 7) * 128;
    int m0 = ((bid2 >> 3) & 1) * 128;
    int b = bid2 >> 4;
    if (tid == 0) {
        while (((volatile unsigned*)g_cnt)[b] < 128u) __nanosleep(200);
    }
    __syncthreads();
    __threadfence();                      // acquire: g_attn stores visible
    sgemm_body(w_out, g_attn + (long)b * 256 * 1024,
               out + (long)b * 512 * 1024 + 256 * 1024,
               256, 1024, m0, n0, 0, sm);
}

// ---------------- launch ----------------------------------------------------
extern "C" void kernel_launch(void* const* d_in, const int* in_sizes, int n_in,
                              void* d_out, int out_size)
{
    const float* x      = (const float*)d_in[0];
    const float* w_qkv  = (const float*)d_in[1];
    const float* w_conv = (const float*)d_in[2];
    const float* w_out  = (const float*)d_in[3];
    const float* krh    = (const float*)d_in[4];
    const float* krw    = (const float*)d_in[5];
    float* out = (float*)d_out;

    float* gq; cudaGetSymbolAddress((void**)&gq, g_qkv);

    int sgB = SG_SMEM_BYTES, atB = ATTN_SMEM_BYTES;
    int bMax = sgB > atB ? sgB : atB;
    cudaFuncSetAttribute(kernelA, cudaFuncAttributeMaxDynamicSharedMemorySize,
                         sgB);
    cudaFuncSetAttribute(kernelB, cudaFuncAttributeMaxDynamicSharedMemorySize,
                         bMax);

    // A) qkv projection + im2col + counter reset (independent, grid-merged)
    kernelA<<<640 + 1152, 256, sgB>>>(w_qkv, x, gq);

    // B) conv GEMM + attention + gated w_out GEMM (single launch)
    kernelB<<<128 + 1024 + 128, 256, bMax>>>(krh, krw, w_conv, w_out, out);
}